// round 1
// baseline (speedup 1.0000x reference)
#include <cuda_runtime.h>
#include <mma.h>
#include <math.h>

using namespace nvcuda;

// Problem constants
#define BB 2
#define TT 2048
#define CC 1024
#define HH 16
#define HD 64
#define MTOT (BB * TT)  // 4096

// ---------------- scratch (device globals; no allocations allowed) ---------
__device__ float g_Q[(size_t)BB * HH * TT * HD];
__device__ float g_K[(size_t)BB * HH * TT * HD];
__device__ float g_V[(size_t)BB * HH * TT * HD];
__device__ float g_Y[(size_t)MTOT * CC];

// ============================================================================
// GEMM: out = X[M,K] @ W[K,N] + bias, tf32 wmma, tiles 128x64x32
// MODE 0: scatter output to head layout [B,H,T,HD] (N-tile == one head)
// MODE 1: plain row-major [M,N]
// ============================================================================
#define GM_TM 128
#define GM_TN 64
#define GM_TK 32
#define AS_LD 40   // 32 + 8 pad
#define BS_LD 72   // 64 + 8 pad

template <int MODE>
__global__ __launch_bounds__(256) void gemm_tf32_kernel(
    const float* __restrict__ X, const float* __restrict__ W,
    const float* __restrict__ bias, float* __restrict__ out)
{
    extern __shared__ float sm[];
    float* As = sm;                    // 128*40 = 5120 floats
    float* Bs = sm + GM_TM * AS_LD;    // 32*72  = 2304 floats
    // epilogue aliases sm[0 .. 8192)

    const int tid  = threadIdx.x;
    const int warp = tid >> 5;
    const int wm   = warp & 3;   // 4 warps along M (32 rows each)
    const int wn   = warp >> 2;  // 2 warps along N (32 cols each)
    const int m0   = blockIdx.y * GM_TM;
    const int n0   = blockIdx.x * GM_TN;

    wmma::fragment<wmma::accumulator, 16, 16, 8, float> acc[2][2];
#pragma unroll
    for (int i = 0; i < 2; i++)
#pragma unroll
        for (int j = 0; j < 2; j++) wmma::fill_fragment(acc[i][j], 0.0f);

    const int ar  = tid >> 3;
    const int ac4 = (tid & 7) * 4;
    const int br  = tid >> 4;
    const int bc4 = (tid & 15) * 4;

    for (int k0 = 0; k0 < CC; k0 += GM_TK) {
        // load X tile [128 x 32]
#pragma unroll
        for (int it = 0; it < 4; it++) {
            int r = ar + it * 32;
            *(float4*)&As[r * AS_LD + ac4] =
                *(const float4*)&X[(size_t)(m0 + r) * CC + k0 + ac4];
        }
        // load W tile [32 x 64]
#pragma unroll
        for (int it = 0; it < 2; it++) {
            int kk = br + it * 16;
            *(float4*)&Bs[kk * BS_LD + bc4] =
                *(const float4*)&W[(size_t)(k0 + kk) * CC + n0 + bc4];
        }
        __syncthreads();

#pragma unroll
        for (int ks = 0; ks < 4; ks++) {
            wmma::fragment<wmma::matrix_a, 16, 16, 8, wmma::precision::tf32,
                           wmma::row_major> a[2];
            wmma::fragment<wmma::matrix_b, 16, 16, 8, wmma::precision::tf32,
                           wmma::row_major> b[2];
#pragma unroll
            for (int i = 0; i < 2; i++) {
                wmma::load_matrix_sync(a[i], &As[(wm * 32 + i * 16) * AS_LD + ks * 8], AS_LD);
#pragma unroll
                for (int t = 0; t < a[i].num_elements; t++)
                    a[i].x[t] = wmma::__float_to_tf32(a[i].x[t]);
            }
#pragma unroll
            for (int j = 0; j < 2; j++) {
                wmma::load_matrix_sync(b[j], &Bs[(ks * 8) * BS_LD + wn * 32 + j * 16], BS_LD);
#pragma unroll
                for (int t = 0; t < b[j].num_elements; t++)
                    b[j].x[t] = wmma::__float_to_tf32(b[j].x[t]);
            }
#pragma unroll
            for (int i = 0; i < 2; i++)
#pragma unroll
                for (int j = 0; j < 2; j++)
                    wmma::mma_sync(acc[i][j], a[i], b[j], acc[i][j]);
        }
        __syncthreads();
    }

    // epilogue: stage in smem (aliased), add bias, scatter
#pragma unroll
    for (int i = 0; i < 2; i++)
#pragma unroll
        for (int j = 0; j < 2; j++)
            wmma::store_matrix_sync(&sm[(wm * 32 + i * 16) * GM_TN + wn * 32 + j * 16],
                                    acc[i][j], GM_TN, wmma::mem_row_major);
    __syncthreads();

#pragma unroll
    for (int it = 0; it < 8; it++) {
        int idx4 = tid + it * 256;
        int r    = idx4 >> 4;
        int c    = (idx4 & 15) * 4;
        float4 v  = *(float4*)&sm[r * GM_TN + c];
        float4 bv = *(const float4*)&bias[n0 + c];
        v.x += bv.x; v.y += bv.y; v.z += bv.z; v.w += bv.w;
        if (MODE == 0) {
            // row m0+r -> (b, t); col block -> head h = blockIdx.x; c = d
            int bidx = m0 >> 11;                 // /2048
            int t    = (m0 - (bidx << 11)) + r;  // 128 | 2048 so no batch crossing
            size_t off = (((size_t)(bidx * HH) + blockIdx.x) * TT + t) * HD + c;
            *(float4*)&out[off] = v;
        } else {
            *(float4*)&out[(size_t)(m0 + r) * CC + n0 + c] = v;
        }
    }
}

// ============================================================================
// Flash attention (causal), tf32 wmma. One 64-row q-tile per CTA.
// softmax(S/8) with online max/sum; O accumulated in smem fp32.
// ============================================================================
#define ALD 68  // 64 + 4 pad, multiple of 4 for wmma ldm

__global__ __launch_bounds__(256) void attn_kernel(
    const float* __restrict__ Q, const float* __restrict__ K,
    const float* __restrict__ V, float* __restrict__ Y)
{
    extern __shared__ float sm[];
    float* q_s = sm;                 // 64*68
    float* k_s = q_s + 64 * ALD;     // 64*68
    float* v_s = k_s + 64 * ALD;     // 64*68
    float* s_s = v_s + 64 * ALD;     // 64*68 (S then P)
    float* t_s = s_s + 64 * ALD;     // 64*68 (PV partial)
    float* o_s = t_s + 64 * ALD;     // 64*64
    float* m_s = o_s + 64 * 64;      // 64
    float* l_s = m_s + 64;           // 64
    float* c_s = l_s + 64;           // 64

    const int tid  = threadIdx.x;
    const int warp = tid >> 5;
    const int wm   = warp >> 1;  // 4 row strips of 16
    const int wn   = warp & 1;   // 2 col groups of 32

    const int bh = blockIdx.y;
    const int qt = (int)gridDim.x - 1 - (int)blockIdx.x;  // heavy tiles first
    const int q0 = qt * 64;

    const float* Qb = Q + ((size_t)bh * TT + q0) * HD;

    // init state + load Q tile
#pragma unroll
    for (int it = 0; it < 16; it++) o_s[tid + it * 256] = 0.0f;
    if (tid < 64) { m_s[tid] = -INFINITY; l_s[tid] = 0.0f; }
#pragma unroll
    for (int it = 0; it < 4; it++) {
        int idx4 = tid + it * 256;
        int r = idx4 >> 4, c4 = (idx4 & 15) * 4;
        *(float4*)&q_s[r * ALD + c4] = *(const float4*)&Qb[r * HD + c4];
    }
    __syncthreads();

    for (int kt = 0; kt <= qt; kt++) {
        const float* Kb = K + ((size_t)bh * TT + kt * 64) * HD;
        const float* Vb = V + ((size_t)bh * TT + kt * 64) * HD;
#pragma unroll
        for (int it = 0; it < 4; it++) {
            int idx4 = tid + it * 256;
            int r = idx4 >> 4, c4 = (idx4 & 15) * 4;
            *(float4*)&k_s[r * ALD + c4] = *(const float4*)&Kb[r * HD + c4];
            *(float4*)&v_s[r * ALD + c4] = *(const float4*)&Vb[r * HD + c4];
        }
        __syncthreads();

        // ---- S = Q K^T (64x64x64) ----
        {
            wmma::fragment<wmma::accumulator, 16, 16, 8, float> acc[2];
            wmma::fill_fragment(acc[0], 0.0f);
            wmma::fill_fragment(acc[1], 0.0f);
#pragma unroll
            for (int ks = 0; ks < 8; ks++) {
                wmma::fragment<wmma::matrix_a, 16, 16, 8, wmma::precision::tf32,
                               wmma::row_major> a;
                wmma::load_matrix_sync(a, &q_s[(wm * 16) * ALD + ks * 8], ALD);
#pragma unroll
                for (int t = 0; t < a.num_elements; t++)
                    a.x[t] = wmma::__float_to_tf32(a.x[t]);
#pragma unroll
                for (int j = 0; j < 2; j++) {
                    wmma::fragment<wmma::matrix_b, 16, 16, 8, wmma::precision::tf32,
                                   wmma::col_major> b;
                    wmma::load_matrix_sync(b, &k_s[(wn * 32 + j * 16) * ALD + ks * 8], ALD);
#pragma unroll
                    for (int t = 0; t < b.num_elements; t++)
                        b.x[t] = wmma::__float_to_tf32(b.x[t]);
                    wmma::mma_sync(acc[j], a, b, acc[j]);
                }
            }
#pragma unroll
            for (int j = 0; j < 2; j++)
                wmma::store_matrix_sync(&s_s[(wm * 16) * ALD + wn * 32 + j * 16],
                                        acc[j], ALD, wmma::mem_row_major);
        }
        __syncthreads();

        // ---- online softmax update (scale 1/sqrt(64) = 0.125) ----
        if (tid < 64) {
            int r = tid;
            float* srow = &s_s[r * ALD];
            int jmax = (kt == qt) ? (r + 1) : 64;  // causal: diagonal tile only
            float mold = m_s[r];
            float mx = mold;
            for (int j = 0; j < jmax; j++) {
                float v = srow[j] * 0.125f;
                mx = fmaxf(mx, v);
            }
            float corr = __expf(mold - mx);  // 0 on first tile (mold = -inf)
            float sum = 0.0f;
#pragma unroll 4
            for (int j = 0; j < 64; j++) {
                float p = (j < jmax) ? __expf(srow[j] * 0.125f - mx) : 0.0f;
                srow[j] = p;
                sum += p;
            }
            m_s[r] = mx;
            l_s[r] = l_s[r] * corr + sum;
            c_s[r] = corr;
        }
        __syncthreads();

        // rescale O by correction factor
#pragma unroll
        for (int it = 0; it < 16; it++) {
            int e = tid + it * 256;
            o_s[e] *= c_s[e >> 6];
        }

        // ---- T = P V (64x64x64) ----
        {
            wmma::fragment<wmma::accumulator, 16, 16, 8, float> acc[2];
            wmma::fill_fragment(acc[0], 0.0f);
            wmma::fill_fragment(acc[1], 0.0f);
#pragma unroll
            for (int ks = 0; ks < 8; ks++) {
                wmma::fragment<wmma::matrix_a, 16, 16, 8, wmma::precision::tf32,
                               wmma::row_major> a;
                wmma::load_matrix_sync(a, &s_s[(wm * 16) * ALD + ks * 8], ALD);
#pragma unroll
                for (int t = 0; t < a.num_elements; t++)
                    a.x[t] = wmma::__float_to_tf32(a.x[t]);
#pragma unroll
                for (int j = 0; j < 2; j++) {
                    wmma::fragment<wmma::matrix_b, 16, 16, 8, wmma::precision::tf32,
                                   wmma::row_major> b;
                    wmma::load_matrix_sync(b, &v_s[(ks * 8) * ALD + wn * 32 + j * 16], ALD);
#pragma unroll
                    for (int t = 0; t < b.num_elements; t++)
                        b.x[t] = wmma::__float_to_tf32(b.x[t]);
                    wmma::mma_sync(acc[j], a, b, acc[j]);
                }
            }
#pragma unroll
            for (int j = 0; j < 2; j++)
                wmma::store_matrix_sync(&t_s[(wm * 16) * ALD + wn * 32 + j * 16],
                                        acc[j], ALD, wmma::mem_row_major);
        }
        __syncthreads();

        // O += T
#pragma unroll
        for (int it = 0; it < 16; it++) {
            int e = tid + it * 256;
            o_s[e] += t_s[(e >> 6) * ALD + (e & 63)];
        }
        __syncthreads();
    }

    // ---- write Y in [B,T,C] layout ----
    const int b = bh >> 4, h = bh & 15;
    float* Yb = Y + ((size_t)(b * TT + q0)) * CC + h * HD;
#pragma unroll
    for (int it = 0; it < 16; it++) {
        int e = tid + it * 256;
        int r = e >> 6, c = e & 63;
        Yb[(size_t)r * CC + c] = o_s[e] * (1.0f / l_s[r]);
    }
}

// ============================================================================
// launch
// ============================================================================
extern "C" void kernel_launch(void* const* d_in, const int* in_sizes, int n_in,
                              void* d_out, int out_size)
{
    const float* query = (const float*)d_in[0];
    const float* key_  = (const float*)d_in[1];
    const float* value = (const float*)d_in[2];
    // d_in[3] = att_mask (causal tril — implemented analytically, unused)
    const float* Wq = (const float*)d_in[4];
    const float* bq = (const float*)d_in[5];
    const float* Wk = (const float*)d_in[6];
    const float* bk = (const float*)d_in[7];
    const float* Wv = (const float*)d_in[8];
    const float* bv = (const float*)d_in[9];
    const float* Wp = (const float*)d_in[10];
    const float* bp = (const float*)d_in[11];
    float* out = (float*)d_out;

    float *Qp, *Kp, *Vp, *Yp;
    cudaGetSymbolAddress((void**)&Qp, g_Q);
    cudaGetSymbolAddress((void**)&Kp, g_K);
    cudaGetSymbolAddress((void**)&Vp, g_V);
    cudaGetSymbolAddress((void**)&Yp, g_Y);

    const int gemm_smem = 8192 * 4;  // max(load tiles, epilogue stage) = 32 KB
    const int attn_smem = (64 * ALD * 5 + 64 * 64 + 3 * 64) * 4;  // 104192 B

    cudaFuncSetAttribute((const void*)attn_kernel,
                         cudaFuncAttributeMaxDynamicSharedMemorySize, attn_smem);

    dim3 ggrid(CC / GM_TN, MTOT / GM_TM);  // (16, 32)
    gemm_tf32_kernel<0><<<ggrid, 256, gemm_smem>>>(query, Wq, bq, Qp);
    gemm_tf32_kernel<0><<<ggrid, 256, gemm_smem>>>(key_, Wk, bk, Kp);
    gemm_tf32_kernel<0><<<ggrid, 256, gemm_smem>>>(value, Wv, bv, Vp);

    attn_kernel<<<dim3(TT / 64, BB * HH), 256, attn_smem>>>(Qp, Kp, Vp, Yp);

    gemm_tf32_kernel<1><<<ggrid, 256, gemm_smem>>>(Yp, Wp, bp, out);
}

// round 2
// speedup vs baseline: 1.1483x; 1.1483x over previous
#include <cuda_runtime.h>
#include <mma.h>
#include <math.h>

using namespace nvcuda;

#define BB 2
#define TT 2048
#define CC 1024
#define HH 16
#define HD 64
#define MTOT (BB * TT)  // 4096

// ---------------- scratch ----------------
__device__ float g_Q[(size_t)BB * HH * TT * HD];
__device__ float g_K[(size_t)BB * HH * TT * HD];
__device__ float g_V[(size_t)BB * HH * TT * HD];
__device__ float g_Y[(size_t)MTOT * CC];

// ---------------- cp.async helpers ----------------
__device__ __forceinline__ void cp16(void* smem_dst, const void* gsrc) {
    unsigned sd = (unsigned)__cvta_generic_to_shared(smem_dst);
    asm volatile("cp.async.cg.shared.global [%0], [%1], 16;\n" :: "r"(sd), "l"(gsrc));
}
#define CP_COMMIT asm volatile("cp.async.commit_group;\n" ::: "memory")
#define CP_WAIT0  asm volatile("cp.async.wait_group 0;\n" ::: "memory")
#define CP_WAIT1  asm volatile("cp.async.wait_group 1;\n" ::: "memory")

// ============================================================================
// GEMM body: out = X[M,1024] @ W[1024,N-tile] + bias.  Tiles 128x128x32,
// 8 warps (4 along M x 2 along N, 32x64 per warp), tf32 wmma, cp.async 2-stage.
// ============================================================================
#define GA_LD 40    // 32 + 8
#define GB_LD 136   // 128 + 8
#define GSTAGE (128 * GA_LD + 32 * GB_LD)  // floats per stage = 9472

template <bool SCATTER>
__device__ __forceinline__ void gemm_body(
    const float* __restrict__ X, const float* __restrict__ W,
    const float* __restrict__ bias, float* __restrict__ out)
{
    extern __shared__ float sm[];
    const int tid  = threadIdx.x;
    const int warp = tid >> 5;
    const int wm   = warp >> 1;   // 0..3
    const int wn   = warp & 1;    // 0..1
    const int m0   = blockIdx.y * 128;
    const int n0   = blockIdx.x * 128;

    wmma::fragment<wmma::accumulator, 16, 16, 8, float> acc[2][4];
#pragma unroll
    for (int i = 0; i < 2; i++)
#pragma unroll
        for (int j = 0; j < 4; j++) wmma::fill_fragment(acc[i][j], 0.0f);

    const int ar  = tid >> 3;        // 0..31
    const int ac4 = (tid & 7) * 4;
    const int br  = tid >> 5;        // 0..7
    const int bc4 = (tid & 31) * 4;

    auto issue = [&](int k0, int s) {
        float* As = sm + s * GSTAGE;
        float* Bs = As + 128 * GA_LD;
#pragma unroll
        for (int it = 0; it < 4; it++) {
            int r = ar + it * 32;
            cp16(&As[r * GA_LD + ac4], &X[(size_t)(m0 + r) * CC + k0 + ac4]);
        }
#pragma unroll
        for (int it = 0; it < 4; it++) {
            int kk = br + it * 8;
            cp16(&Bs[kk * GB_LD + bc4], &W[(size_t)(k0 + kk) * CC + n0 + bc4]);
        }
        CP_COMMIT;
    };

    issue(0, 0);
    const int NK = CC / 32;  // 32
    for (int kt = 0; kt < NK; kt++) {
        int s = kt & 1;
        if (kt + 1 < NK) { issue((kt + 1) * 32, s ^ 1); CP_WAIT1; }
        else             { CP_WAIT0; }
        __syncthreads();

        float* As = sm + s * GSTAGE;
        float* Bs = As + 128 * GA_LD;
#pragma unroll
        for (int ks = 0; ks < 4; ks++) {
            wmma::fragment<wmma::matrix_a, 16, 16, 8, wmma::precision::tf32,
                           wmma::row_major> a[2];
            wmma::fragment<wmma::matrix_b, 16, 16, 8, wmma::precision::tf32,
                           wmma::row_major> b[4];
#pragma unroll
            for (int i = 0; i < 2; i++) {
                wmma::load_matrix_sync(a[i], &As[(wm * 32 + i * 16) * GA_LD + ks * 8], GA_LD);
#pragma unroll
                for (int t = 0; t < a[i].num_elements; t++)
                    a[i].x[t] = wmma::__float_to_tf32(a[i].x[t]);
            }
#pragma unroll
            for (int j = 0; j < 4; j++) {
                wmma::load_matrix_sync(b[j], &Bs[(ks * 8) * GB_LD + wn * 64 + j * 16], GB_LD);
#pragma unroll
                for (int t = 0; t < b[j].num_elements; t++)
                    b[j].x[t] = wmma::__float_to_tf32(b[j].x[t]);
            }
#pragma unroll
            for (int i = 0; i < 2; i++)
#pragma unroll
                for (int j = 0; j < 4; j++)
                    wmma::mma_sync(acc[i][j], a[i], b[j], acc[i][j]);
        }
        __syncthreads();
    }

    // epilogue: stage 128x128 in smem (aliased)
#pragma unroll
    for (int i = 0; i < 2; i++)
#pragma unroll
        for (int j = 0; j < 4; j++)
            wmma::store_matrix_sync(&sm[(wm * 32 + i * 16) * 128 + wn * 64 + j * 16],
                                    acc[i][j], 128, wmma::mem_row_major);
    __syncthreads();

#pragma unroll
    for (int it = 0; it < 16; it++) {
        int idx4 = tid + it * 256;
        int r    = idx4 >> 5;
        int c    = (idx4 & 31) * 4;
        float4 v  = *(float4*)&sm[r * 128 + c];
        float4 bv = *(const float4*)&bias[n0 + c];
        v.x += bv.x; v.y += bv.y; v.z += bv.z; v.w += bv.w;
        if (SCATTER) {
            int h = blockIdx.x * 2 + (c >> 6);
            int d = c & 63;
            int b = m0 >> 11;
            int t = (m0 & 2047) + r;
            *(float4*)&out[(((size_t)(b * HH + h)) * TT + t) * HD + d] = v;
        } else {
            *(float4*)&out[(size_t)(m0 + r) * CC + n0 + c] = v;
        }
    }
}

struct QKVArgs {
    const float* X[3];
    const float* W[3];
    const float* Bv[3];
    float* O[3];
};

__global__ __launch_bounds__(256) void gemm_qkv_kernel(QKVArgs args) {
    int z = blockIdx.z;
    gemm_body<true>(args.X[z], args.W[z], args.Bv[z], args.O[z]);
}

__global__ __launch_bounds__(256) void gemm_proj_kernel(
    const float* __restrict__ X, const float* __restrict__ W,
    const float* __restrict__ bias, float* __restrict__ out) {
    gemm_body<false>(X, W, bias, out);
}

// ============================================================================
// Flash attention (causal), tf32 wmma, 64-row q-tiles, cp.async 2-stage K/V,
// parallel softmax (4 threads/row), O accumulated in registers.
// ============================================================================
#define ALD 68

__global__ __launch_bounds__(256) void attn_kernel(
    const float* __restrict__ Q, const float* __restrict__ K,
    const float* __restrict__ V, float* __restrict__ Y)
{
    extern __shared__ float sm[];
    float* q_s = sm;                       // 64*68
    float* k_s = q_s + 64 * ALD;           // 2 * 64*68
    float* v_s = k_s + 2 * 64 * ALD;       // 2 * 64*68
    float* s_s = v_s + 2 * 64 * ALD;       // 64*68
    float* t_s = s_s + 64 * ALD;           // 64*68
    float* m_s = t_s + 64 * ALD;           // 64
    float* l_s = m_s + 64;                 // 64
    float* c_s = l_s + 64;                 // 64

    const int tid  = threadIdx.x;
    const int warp = tid >> 5;
    const int wm   = warp >> 1;  // 4 row strips of 16
    const int wn   = warp & 1;   // 2 col groups of 32

    const int bh = blockIdx.y;
    const int qt = (int)gridDim.x - 1 - (int)blockIdx.x;  // heavy tiles first
    const int q0 = qt * 64;

    float o[16];
#pragma unroll
    for (int i = 0; i < 16; i++) o[i] = 0.0f;
    // element map: it -> row r = (tid>>6) + it*4, col c = tid & 63
    const int orow = tid >> 6;
    const int ocol = tid & 63;

    if (tid < 64) { m_s[tid] = -INFINITY; l_s[tid] = 0.0f; }

    // load Q tile (plain)
    const float* Qb = Q + ((size_t)bh * TT + q0) * HD;
#pragma unroll
    for (int it = 0; it < 4; it++) {
        int idx4 = tid + it * 256;
        int r = idx4 >> 4, c4 = (idx4 & 15) * 4;
        *(float4*)&q_s[r * ALD + c4] = *(const float4*)&Qb[r * HD + c4];
    }

    auto issue_kv = [&](int kt, int buf) {
        const float* Kb = K + ((size_t)bh * TT + kt * 64) * HD;
        const float* Vb = V + ((size_t)bh * TT + kt * 64) * HD;
        float* kd = k_s + buf * 64 * ALD;
        float* vd = v_s + buf * 64 * ALD;
#pragma unroll
        for (int it = 0; it < 4; it++) {
            int idx4 = tid + it * 256;
            int r = idx4 >> 4, c4 = (idx4 & 15) * 4;
            cp16(&kd[r * ALD + c4], &Kb[r * HD + c4]);
            cp16(&vd[r * ALD + c4], &Vb[r * HD + c4]);
        }
        CP_COMMIT;
    };

    issue_kv(0, 0);

    for (int kt = 0; kt <= qt; kt++) {
        int buf = kt & 1;
        if (kt + 1 <= qt) { issue_kv(kt + 1, buf ^ 1); CP_WAIT1; }
        else              { CP_WAIT0; }
        __syncthreads();

        float* kb = k_s + buf * 64 * ALD;
        float* vb = v_s + buf * 64 * ALD;

        // ---- S = Q K^T ----
        {
            wmma::fragment<wmma::accumulator, 16, 16, 8, float> acc[2];
            wmma::fill_fragment(acc[0], 0.0f);
            wmma::fill_fragment(acc[1], 0.0f);
#pragma unroll
            for (int ks = 0; ks < 8; ks++) {
                wmma::fragment<wmma::matrix_a, 16, 16, 8, wmma::precision::tf32,
                               wmma::row_major> a;
                wmma::load_matrix_sync(a, &q_s[(wm * 16) * ALD + ks * 8], ALD);
#pragma unroll
                for (int t = 0; t < a.num_elements; t++)
                    a.x[t] = wmma::__float_to_tf32(a.x[t]);
#pragma unroll
                for (int j = 0; j < 2; j++) {
                    wmma::fragment<wmma::matrix_b, 16, 16, 8, wmma::precision::tf32,
                                   wmma::col_major> b;
                    wmma::load_matrix_sync(b, &kb[(wn * 32 + j * 16) * ALD + ks * 8], ALD);
#pragma unroll
                    for (int t = 0; t < b.num_elements; t++)
                        b.x[t] = wmma::__float_to_tf32(b.x[t]);
                    wmma::mma_sync(acc[j], a, b, acc[j]);
                }
            }
#pragma unroll
            for (int j = 0; j < 2; j++)
                wmma::store_matrix_sync(&s_s[(wm * 16) * ALD + wn * 32 + j * 16],
                                        acc[j], ALD, wmma::mem_row_major);
        }
        __syncthreads();

        // ---- parallel online softmax: 4 threads per row, 16 cols each ----
        {
            int r = tid >> 2;       // 0..63
            int g = tid & 3;        // col group
            float* srow = &s_s[r * ALD + g * 16];
            int jmax = 16;
            if (kt == qt) {
                int lim = r + 1 - g * 16;
                jmax = lim < 0 ? 0 : (lim > 16 ? 16 : lim);
            }
            float mold = m_s[r];
            float mx = -INFINITY;
#pragma unroll
            for (int j = 0; j < 16; j++)
                if (j < jmax) mx = fmaxf(mx, srow[j] * 0.125f);
            mx = fmaxf(mx, __shfl_xor_sync(0xffffffffu, mx, 1));
            mx = fmaxf(mx, __shfl_xor_sync(0xffffffffu, mx, 2));
            mx = fmaxf(mx, mold);
            float sum = 0.0f;
#pragma unroll
            for (int j = 0; j < 16; j++) {
                float p = (j < jmax) ? __expf(srow[j] * 0.125f - mx) : 0.0f;
                srow[j] = p;
                sum += p;
            }
            sum += __shfl_xor_sync(0xffffffffu, sum, 1);
            sum += __shfl_xor_sync(0xffffffffu, sum, 2);
            if (g == 0) {
                float corr = __expf(mold - mx);
                m_s[r] = mx;
                l_s[r] = l_s[r] * corr + sum;
                c_s[r] = corr;
            }
        }
        __syncthreads();

        // ---- rescale O (regs) + T = P V ----
        {
#pragma unroll
            for (int it = 0; it < 16; it++)
                o[it] *= c_s[orow + it * 4];

            wmma::fragment<wmma::accumulator, 16, 16, 8, float> acc[2];
            wmma::fill_fragment(acc[0], 0.0f);
            wmma::fill_fragment(acc[1], 0.0f);
#pragma unroll
            for (int ks = 0; ks < 8; ks++) {
                wmma::fragment<wmma::matrix_a, 16, 16, 8, wmma::precision::tf32,
                               wmma::row_major> a;
                wmma::load_matrix_sync(a, &s_s[(wm * 16) * ALD + ks * 8], ALD);
#pragma unroll
                for (int t = 0; t < a.num_elements; t++)
                    a.x[t] = wmma::__float_to_tf32(a.x[t]);
#pragma unroll
                for (int j = 0; j < 2; j++) {
                    wmma::fragment<wmma::matrix_b, 16, 16, 8, wmma::precision::tf32,
                                   wmma::row_major> b;
                    wmma::load_matrix_sync(b, &vb[(ks * 8) * ALD + wn * 32 + j * 16], ALD);
#pragma unroll
                    for (int t = 0; t < b.num_elements; t++)
                        b.x[t] = wmma::__float_to_tf32(b.x[t]);
                    wmma::mma_sync(acc[j], a, b, acc[j]);
                }
            }
#pragma unroll
            for (int j = 0; j < 2; j++)
                wmma::store_matrix_sync(&t_s[(wm * 16) * ALD + wn * 32 + j * 16],
                                        acc[j], ALD, wmma::mem_row_major);
        }
        __syncthreads();

        // O += T
#pragma unroll
        for (int it = 0; it < 16; it++)
            o[it] += t_s[(orow + it * 4) * ALD + ocol];
        // no trailing sync needed: next iteration's top __syncthreads covers it
    }

    // final normalize + write Y in [B,T,C]
    if (tid < 64) c_s[tid] = 1.0f / l_s[tid];
    __syncthreads();
    const int b = bh >> 4, h = bh & 15;
    float* Yb = Y + ((size_t)(b * TT + q0)) * CC + h * HD;
#pragma unroll
    for (int it = 0; it < 16; it++) {
        int r = orow + it * 4;
        Yb[(size_t)r * CC + ocol] = o[it] * c_s[r];
    }
}

// ============================================================================
// launch
// ============================================================================
extern "C" void kernel_launch(void* const* d_in, const int* in_sizes, int n_in,
                              void* d_out, int out_size)
{
    const float* query = (const float*)d_in[0];
    const float* key_  = (const float*)d_in[1];
    const float* value = (const float*)d_in[2];
    const float* Wq = (const float*)d_in[4];
    const float* bq = (const float*)d_in[5];
    const float* Wk = (const float*)d_in[6];
    const float* bk = (const float*)d_in[7];
    const float* Wv = (const float*)d_in[8];
    const float* bv = (const float*)d_in[9];
    const float* Wp = (const float*)d_in[10];
    const float* bp = (const float*)d_in[11];
    float* out = (float*)d_out;

    float *Qp, *Kp, *Vp, *Yp;
    cudaGetSymbolAddress((void**)&Qp, g_Q);
    cudaGetSymbolAddress((void**)&Kp, g_K);
    cudaGetSymbolAddress((void**)&Vp, g_V);
    cudaGetSymbolAddress((void**)&Yp, g_Y);

    const int gemm_smem = 2 * GSTAGE * 4;                      // 75776
    const int attn_smem = (7 * 64 * ALD + 3 * 64) * 4;         // 122624

    static bool attr_done = false;
    if (!attr_done) {
        cudaFuncSetAttribute((const void*)gemm_qkv_kernel,
                             cudaFuncAttributeMaxDynamicSharedMemorySize, gemm_smem);
        cudaFuncSetAttribute((const void*)gemm_proj_kernel,
                             cudaFuncAttributeMaxDynamicSharedMemorySize, gemm_smem);
        cudaFuncSetAttribute((const void*)attn_kernel,
                             cudaFuncAttributeMaxDynamicSharedMemorySize, attn_smem);
        attr_done = true;
    }

    QKVArgs args;
    args.X[0] = query; args.X[1] = key_; args.X[2] = value;
    args.W[0] = Wq;    args.W[1] = Wk;   args.W[2] = Wv;
    args.Bv[0] = bq;   args.Bv[1] = bk;  args.Bv[2] = bv;
    args.O[0] = Qp;    args.O[1] = Kp;   args.O[2] = Vp;

    gemm_qkv_kernel<<<dim3(CC / 128, MTOT / 128, 3), 256, gemm_smem>>>(args);
    attn_kernel<<<dim3(TT / 64, BB * HH), 256, attn_smem>>>(Qp, Kp, Vp, Yp);
    gemm_proj_kernel<<<dim3(CC / 128, MTOT / 128), 256, gemm_smem>>>(Yp, Wp, bp, out);
}

// round 4
// speedup vs baseline: 1.7391x; 1.5145x over previous
#include <cuda_runtime.h>
#include <mma.h>
#include <math.h>
#include <stdint.h>

using namespace nvcuda;

#define BB 2
#define TT 2048
#define CC 1024
#define HH 16
#define HD 64
#define MTOT (BB * TT)  // 4096

// ---------------- scratch ----------------
__device__ float g_Q[(size_t)BB * HH * TT * HD];
__device__ float g_K[(size_t)BB * HH * TT * HD];
__device__ float g_V[(size_t)BB * HH * TT * HD];
__device__ float g_Y[(size_t)MTOT * CC];

// ---------------- helpers ----------------
__device__ __forceinline__ void cp16(void* smem_dst, const void* gsrc) {
    unsigned sd = (unsigned)__cvta_generic_to_shared(smem_dst);
    asm volatile("cp.async.cg.shared.global [%0], [%1], 16;\n" :: "r"(sd), "l"(gsrc));
}
#define CP_COMMIT asm volatile("cp.async.commit_group;\n" ::: "memory")
#define CP_WAIT0  asm volatile("cp.async.wait_group 0;\n" ::: "memory")
#define CP_WAIT1  asm volatile("cp.async.wait_group 1;\n" ::: "memory")

__device__ __forceinline__ float f2tf32(float x) {
    float r;
    asm("cvt.rna.tf32.f32 %0, %1;" : "=f"(r) : "f"(x));
    return r;
}
__device__ __forceinline__ float fexp2(float x) {
    float y;
    asm("ex2.approx.f32 %0, %1;" : "=f"(y) : "f"(x));
    return y;
}

// m16n8k8 tf32 mma, row.col, f32 accum
__device__ __forceinline__ void mma_tf32(float* d, const uint32_t* a,
                                         uint32_t b0, uint32_t b1) {
    asm volatile(
        "mma.sync.aligned.m16n8k8.row.col.f32.tf32.tf32.f32 "
        "{%0,%1,%2,%3}, {%4,%5,%6,%7}, {%8,%9}, {%0,%1,%2,%3};"
        : "+f"(d[0]), "+f"(d[1]), "+f"(d[2]), "+f"(d[3])
        : "r"(a[0]), "r"(a[1]), "r"(a[2]), "r"(a[3]), "r"(b0), "r"(b1));
}

// ============================================================================
// GEMM (wmma tf32, 128x128x32, cp.async 2-stage). SCATTER epilogue also
// rounds outputs to tf32 so the attention kernel needs no cvt in its mainloop.
// ============================================================================
#define GA_LD 40
#define GB_LD 136
#define GSTAGE (128 * GA_LD + 32 * GB_LD)  // 9472 floats

template <bool SCATTER>
__device__ __forceinline__ void gemm_body(
    const float* __restrict__ X, const float* __restrict__ W,
    const float* __restrict__ bias, float* __restrict__ out)
{
    extern __shared__ float sm[];
    const int tid  = threadIdx.x;
    const int warp = tid >> 5;
    const int wm   = warp >> 1;
    const int wn   = warp & 1;
    const int m0   = blockIdx.y * 128;
    const int n0   = blockIdx.x * 128;

    wmma::fragment<wmma::accumulator, 16, 16, 8, float> acc[2][4];
#pragma unroll
    for (int i = 0; i < 2; i++)
#pragma unroll
        for (int j = 0; j < 4; j++) wmma::fill_fragment(acc[i][j], 0.0f);

    const int ar  = tid >> 3;
    const int ac4 = (tid & 7) * 4;
    const int br  = tid >> 5;
    const int bc4 = (tid & 31) * 4;

    auto issue = [&](int k0, int s) {
        float* As = sm + s * GSTAGE;
        float* Bs = As + 128 * GA_LD;
#pragma unroll
        for (int it = 0; it < 4; it++) {
            int r = ar + it * 32;
            cp16(&As[r * GA_LD + ac4], &X[(size_t)(m0 + r) * CC + k0 + ac4]);
        }
#pragma unroll
        for (int it = 0; it < 4; it++) {
            int kk = br + it * 8;
            cp16(&Bs[kk * GB_LD + bc4], &W[(size_t)(k0 + kk) * CC + n0 + bc4]);
        }
        CP_COMMIT;
    };

    issue(0, 0);
    const int NK = CC / 32;
    for (int kt = 0; kt < NK; kt++) {
        int s = kt & 1;
        if (kt + 1 < NK) { issue((kt + 1) * 32, s ^ 1); CP_WAIT1; }
        else             { CP_WAIT0; }
        __syncthreads();

        float* As = sm + s * GSTAGE;
        float* Bs = As + 128 * GA_LD;
#pragma unroll
        for (int ks = 0; ks < 4; ks++) {
            wmma::fragment<wmma::matrix_a, 16, 16, 8, wmma::precision::tf32,
                           wmma::row_major> a[2];
            wmma::fragment<wmma::matrix_b, 16, 16, 8, wmma::precision::tf32,
                           wmma::row_major> b[4];
#pragma unroll
            for (int i = 0; i < 2; i++) {
                wmma::load_matrix_sync(a[i], &As[(wm * 32 + i * 16) * GA_LD + ks * 8], GA_LD);
#pragma unroll
                for (int t = 0; t < a[i].num_elements; t++)
                    a[i].x[t] = wmma::__float_to_tf32(a[i].x[t]);
            }
#pragma unroll
            for (int j = 0; j < 4; j++) {
                wmma::load_matrix_sync(b[j], &Bs[(ks * 8) * GB_LD + wn * 64 + j * 16], GB_LD);
#pragma unroll
                for (int t = 0; t < b[j].num_elements; t++)
                    b[j].x[t] = wmma::__float_to_tf32(b[j].x[t]);
            }
#pragma unroll
            for (int i = 0; i < 2; i++)
#pragma unroll
                for (int j = 0; j < 4; j++)
                    wmma::mma_sync(acc[i][j], a[i], b[j], acc[i][j]);
        }
        __syncthreads();
    }

#pragma unroll
    for (int i = 0; i < 2; i++)
#pragma unroll
        for (int j = 0; j < 4; j++)
            wmma::store_matrix_sync(&sm[(wm * 32 + i * 16) * 128 + wn * 64 + j * 16],
                                    acc[i][j], 128, wmma::mem_row_major);
    __syncthreads();

#pragma unroll
    for (int it = 0; it < 16; it++) {
        int idx4 = tid + it * 256;
        int r    = idx4 >> 5;
        int c    = (idx4 & 31) * 4;
        float4 v  = *(float4*)&sm[r * 128 + c];
        float4 bv = *(const float4*)&bias[n0 + c];
        v.x += bv.x; v.y += bv.y; v.z += bv.z; v.w += bv.w;
        if (SCATTER) {
            v.x = f2tf32(v.x); v.y = f2tf32(v.y); v.z = f2tf32(v.z); v.w = f2tf32(v.w);
            int h = blockIdx.x * 2 + (c >> 6);
            int d = c & 63;
            int b = m0 >> 11;
            int t = (m0 & 2047) + r;
            *(float4*)&out[(((size_t)(b * HH + h)) * TT + t) * HD + d] = v;
        } else {
            *(float4*)&out[(size_t)(m0 + r) * CC + n0 + c] = v;
        }
    }
}

struct QKVArgs {
    const float* X[3];
    const float* Bv[3];
    float* O[3];
    const float* W[3];
};

__global__ __launch_bounds__(256) void gemm_qkv_kernel(QKVArgs args) {
    int z = blockIdx.z;
    gemm_body<true>(args.X[z], args.W[z], args.Bv[z], args.O[z]);
}

__global__ __launch_bounds__(256) void gemm_proj_kernel(
    const float* __restrict__ X, const float* __restrict__ W,
    const float* __restrict__ bias, float* __restrict__ out) {
    gemm_body<false>(X, W, bias, out);
}

// ============================================================================
// Flash attention v3: mma.sync tf32, warp-private rows.
// CTA = 128 q-rows, 8 warps x 16 rows. K-tile 64. One __syncthreads per tile.
// ============================================================================
#define BRQ 128
#define QPLD 68
#define KLD  68
#define VLD  72
#define CSCL 0.18033688f  // 0.125 * log2(e)

#define ATTN_SMEM ((BRQ * QPLD + 2 * 64 * KLD + 2 * 64 * VLD) * 4)

__global__ __launch_bounds__(256) void attn_kernel(
    const float* __restrict__ Q, const float* __restrict__ K,
    const float* __restrict__ V, float* __restrict__ Y)
{
    extern __shared__ float sm[];
    float* qp_s = sm;
    float* k_s  = qp_s + BRQ * QPLD;
    float* v_s  = k_s + 2 * 64 * KLD;

    const int tid  = threadIdx.x;
    const int lane = tid & 31;
    const int w    = tid >> 5;
    const int g    = lane >> 2;
    const int t    = lane & 3;
    const int w16  = w * 16;

    const int bh = blockIdx.y;
    const int qt = (int)gridDim.x - 1 - (int)blockIdx.x;
    const int q0 = qt * BRQ;
    const int nkt = 2 * qt + 2;

    {
        const float* Kb = K + ((size_t)bh * TT) * HD;
        const float* Vb = V + ((size_t)bh * TT) * HD;
#pragma unroll
        for (int p = 0; p < 4; p++) {
            int id = tid + p * 256;
            int r = id >> 4, c = (id & 15) * 4;
            cp16(&k_s[r * KLD + c], &Kb[r * HD + c]);
            cp16(&v_s[r * VLD + c], &Vb[r * HD + c]);
        }
        CP_COMMIT;
    }

    {
        const float* Qb = Q + ((size_t)bh * TT + q0) * HD;
#pragma unroll
        for (int p = 0; p < 8; p++) {
            int id = tid + p * 256;
            int r = id >> 4, c = (id & 15) * 4;
            *(float4*)&qp_s[r * QPLD + c] = *(const float4*)&Qb[r * HD + c];
        }
    }
    __syncthreads();

    uint32_t qa[8][4];
#pragma unroll
    for (int kb = 0; kb < 8; kb++) {
        qa[kb][0] = __float_as_uint(qp_s[(w16 + g)     * QPLD + kb * 8 + t]);
        qa[kb][1] = __float_as_uint(qp_s[(w16 + g + 8) * QPLD + kb * 8 + t]);
        qa[kb][2] = __float_as_uint(qp_s[(w16 + g)     * QPLD + kb * 8 + t + 4]);
        qa[kb][3] = __float_as_uint(qp_s[(w16 + g + 8) * QPLD + kb * 8 + t + 4]);
    }

    float oc[8][4];
#pragma unroll
    for (int i = 0; i < 8; i++)
#pragma unroll
        for (int j = 0; j < 4; j++) oc[i][j] = 0.0f;
    float m0 = -1e30f, m1 = -1e30f, l0 = 0.0f, l1 = 0.0f;

    const int rg0 = q0 + w16 + g;
    const int rg1 = rg0 + 8;

    for (int kt = 0; kt < nkt; kt++) {
        const int buf = kt & 1;
        CP_WAIT0;
        __syncthreads();

        if (kt + 1 < nkt) {
            const float* Kb = K + ((size_t)bh * TT + (kt + 1) * 64) * HD;
            const float* Vb = V + ((size_t)bh * TT + (kt + 1) * 64) * HD;
            float* kd = k_s + (buf ^ 1) * 64 * KLD;
            float* vd = v_s + (buf ^ 1) * 64 * VLD;
#pragma unroll
            for (int p = 0; p < 4; p++) {
                int id = tid + p * 256;
                int r = id >> 4, c = (id & 15) * 4;
                cp16(&kd[r * KLD + c], &Kb[r * HD + c]);
                cp16(&vd[r * VLD + c], &Vb[r * HD + c]);
            }
            CP_COMMIT;
        }

        const float* kb_s = k_s + buf * 64 * KLD;
        const float* vb_s = v_s + buf * 64 * VLD;

        float sc[8][4];
#pragma unroll
        for (int nb = 0; nb < 8; nb++)
#pragma unroll
            for (int j = 0; j < 4; j++) sc[nb][j] = 0.0f;

#pragma unroll
        for (int kb = 0; kb < 8; kb++) {
#pragma unroll
            for (int nb = 0; nb < 8; nb++) {
                uint32_t b0 = __float_as_uint(kb_s[(nb * 8 + g) * KLD + kb * 8 + t]);
                uint32_t b1 = __float_as_uint(kb_s[(nb * 8 + g) * KLD + kb * 8 + t + 4]);
                mma_tf32(sc[nb], qa[kb], b0, b1);
            }
        }

        if (kt >= nkt - 2) {
            const int kbase = kt * 64;
#pragma unroll
            for (int nb = 0; nb < 8; nb++) {
                int kg = kbase + nb * 8 + 2 * t;
                if (kg > rg0)     sc[nb][0] = -1e30f;
                if (kg + 1 > rg0) sc[nb][1] = -1e30f;
                if (kg > rg1)     sc[nb][2] = -1e30f;
                if (kg + 1 > rg1) sc[nb][3] = -1e30f;
            }
        }

        float rm0 = -1e30f, rm1 = -1e30f;
#pragma unroll
        for (int nb = 0; nb < 8; nb++) {
            rm0 = fmaxf(rm0, fmaxf(sc[nb][0], sc[nb][1]));
            rm1 = fmaxf(rm1, fmaxf(sc[nb][2], sc[nb][3]));
        }
        rm0 = fmaxf(rm0, __shfl_xor_sync(0xffffffffu, rm0, 1));
        rm0 = fmaxf(rm0, __shfl_xor_sync(0xffffffffu, rm0, 2));
        rm1 = fmaxf(rm1, __shfl_xor_sync(0xffffffffu, rm1, 1));
        rm1 = fmaxf(rm1, __shfl_xor_sync(0xffffffffu, rm1, 2));

        float nm0 = fmaxf(m0, rm0 * CSCL);
        float nm1 = fmaxf(m1, rm1 * CSCL);
        float corr0 = fexp2(m0 - nm0);
        float corr1 = fexp2(m1 - nm1);

        float s0 = 0.0f, s1 = 0.0f;
#pragma unroll
        for (int nb = 0; nb < 8; nb++) {
            float p0 = fexp2(sc[nb][0] * CSCL - nm0);
            float p1 = fexp2(sc[nb][1] * CSCL - nm0);
            float p2 = fexp2(sc[nb][2] * CSCL - nm1);
            float p3 = fexp2(sc[nb][3] * CSCL - nm1);
            s0 += p0 + p1;
            s1 += p2 + p3;
            float2 u0 = make_float2(f2tf32(p0), f2tf32(p1));
            float2 u1 = make_float2(f2tf32(p2), f2tf32(p3));
            *(float2*)&qp_s[(w16 + g)     * QPLD + nb * 8 + 2 * t] = u0;
            *(float2*)&qp_s[(w16 + g + 8) * QPLD + nb * 8 + 2 * t] = u1;
        }
        s0 += __shfl_xor_sync(0xffffffffu, s0, 1);
        s0 += __shfl_xor_sync(0xffffffffu, s0, 2);
        s1 += __shfl_xor_sync(0xffffffffu, s1, 1);
        s1 += __shfl_xor_sync(0xffffffffu, s1, 2);

        l0 = l0 * corr0 + s0;
        l1 = l1 * corr1 + s1;
        m0 = nm0;
        m1 = nm1;

#pragma unroll
        for (int db = 0; db < 8; db++) {
            oc[db][0] *= corr0; oc[db][1] *= corr0;
            oc[db][2] *= corr1; oc[db][3] *= corr1;
        }

        __syncwarp();

#pragma unroll
        for (int kb = 0; kb < 8; kb++) {
            uint32_t pa[4];
            pa[0] = __float_as_uint(qp_s[(w16 + g)     * QPLD + kb * 8 + t]);
            pa[1] = __float_as_uint(qp_s[(w16 + g + 8) * QPLD + kb * 8 + t]);
            pa[2] = __float_as_uint(qp_s[(w16 + g)     * QPLD + kb * 8 + t + 4]);
            pa[3] = __float_as_uint(qp_s[(w16 + g + 8) * QPLD + kb * 8 + t + 4]);
#pragma unroll
            for (int db = 0; db < 8; db++) {
                uint32_t b0 = __float_as_uint(vb_s[(kb * 8 + t)     * VLD + db * 8 + g]);
                uint32_t b1 = __float_as_uint(vb_s[(kb * 8 + t + 4) * VLD + db * 8 + g]);
                mma_tf32(oc[db], pa, b0, b1);
            }
        }
        __syncwarp();
    }

    const float r0 = 1.0f / l0;
    const float r1 = 1.0f / l1;
    const int b = bh >> 4, h = bh & 15;
    float* Yb = Y + ((size_t)(b * TT + q0 + w16)) * CC + h * HD;
#pragma unroll
    for (int db = 0; db < 8; db++) {
        float2 u0 = make_float2(oc[db][0] * r0, oc[db][1] * r0);
        float2 u1 = make_float2(oc[db][2] * r1, oc[db][3] * r1);
        *(float2*)&Yb[(size_t)g * CC + db * 8 + 2 * t] = u0;
        *(float2*)&Yb[(size_t)(g + 8) * CC + db * 8 + 2 * t] = u1;
    }
}

// ============================================================================
// launch
// ============================================================================
extern "C" void kernel_launch(void* const* d_in, const int* in_sizes, int n_in,
                              void* d_out, int out_size)
{
    const float* query = (const float*)d_in[0];
    const float* key_  = (const float*)d_in[1];
    const float* value = (const float*)d_in[2];
    const float* Wq = (const float*)d_in[4];
    const float* bq = (const float*)d_in[5];
    const float* Wk = (const float*)d_in[6];
    const float* bk = (const float*)d_in[7];
    const float* Wv = (const float*)d_in[8];
    const float* bv = (const float*)d_in[9];
    const float* Wp = (const float*)d_in[10];
    const float* bp = (const float*)d_in[11];
    float* out = (float*)d_out;

    float *Qp, *Kp, *Vp, *Yp;
    cudaGetSymbolAddress((void**)&Qp, g_Q);
    cudaGetSymbolAddress((void**)&Kp, g_K);
    cudaGetSymbolAddress((void**)&Vp, g_V);
    cudaGetSymbolAddress((void**)&Yp, g_Y);

    const int gemm_smem = 2 * GSTAGE * 4;   // 75776

    static bool attr_done = false;
    if (!attr_done) {
        cudaFuncSetAttribute((const void*)gemm_qkv_kernel,
                             cudaFuncAttributeMaxDynamicSharedMemorySize, gemm_smem);
        cudaFuncSetAttribute((const void*)gemm_proj_kernel,
                             cudaFuncAttributeMaxDynamicSharedMemorySize, gemm_smem);
        cudaFuncSetAttribute((const void*)attn_kernel,
                             cudaFuncAttributeMaxDynamicSharedMemorySize, ATTN_SMEM);
        attr_done = true;
    }

    QKVArgs args;
    args.X[0] = query; args.X[1] = key_; args.X[2] = value;
    args.W[0] = Wq;    args.W[1] = Wk;   args.W[2] = Wv;
    args.Bv[0] = bq;   args.Bv[1] = bk;  args.Bv[2] = bv;
    args.O[0] = Qp;    args.O[1] = Kp;   args.O[2] = Vp;

    gemm_qkv_kernel<<<dim3(CC / 128, MTOT / 128, 3), 256, gemm_smem>>>(args);
    attn_kernel<<<dim3(TT / BRQ, BB * HH), 256, ATTN_SMEM>>>(Qp, Kp, Vp, Yp);
    gemm_proj_kernel<<<dim3(CC / 128, MTOT / 128), 256, gemm_smem>>>(Yp, Wp, bp, out);
}

// round 5
// speedup vs baseline: 2.9669x; 1.7060x over previous
#include <cuda_runtime.h>
#include <math.h>
#include <stdint.h>

#define BB 2
#define TT 2048
#define CC 1024
#define HH 16
#define HD 64
#define MTOT (BB * TT)  // 4096

// ---------------- scratch ----------------
__device__ float g_Q[(size_t)BB * HH * TT * HD];
__device__ float g_K[(size_t)BB * HH * TT * HD];
__device__ float g_V[(size_t)BB * HH * TT * HD];
__device__ float g_Y[(size_t)MTOT * CC];
__device__ float g_Xr[(size_t)3 * MTOT * CC];   // tf32-rounded query/key/value
__device__ float g_Wr[(size_t)4 * CC * CC];     // tf32-rounded weights

// ---------------- helpers ----------------
__device__ __forceinline__ void cp16(void* smem_dst, const void* gsrc) {
    unsigned sd = (unsigned)__cvta_generic_to_shared(smem_dst);
    asm volatile("cp.async.cg.shared.global [%0], [%1], 16;\n" :: "r"(sd), "l"(gsrc));
}
#define CP_COMMIT asm volatile("cp.async.commit_group;\n" ::: "memory")
#define CP_WAIT0  asm volatile("cp.async.wait_group 0;\n" ::: "memory")
#define CP_WAIT1  asm volatile("cp.async.wait_group 1;\n" ::: "memory")

__device__ __forceinline__ float f2tf32(float x) {
    float r;
    asm("cvt.rna.tf32.f32 %0, %1;" : "=f"(r) : "f"(x));
    return r;
}
__device__ __forceinline__ float fexp2(float x) {
    float y;
    asm("ex2.approx.f32 %0, %1;" : "=f"(y) : "f"(x));
    return y;
}

// m16n8k8 tf32 mma, row.col, f32 accum
__device__ __forceinline__ void mma_tf32(float* d, const uint32_t* a,
                                         uint32_t b0, uint32_t b1) {
    asm volatile(
        "mma.sync.aligned.m16n8k8.row.col.f32.tf32.tf32.f32 "
        "{%0,%1,%2,%3}, {%4,%5,%6,%7}, {%8,%9}, {%0,%1,%2,%3};"
        : "+f"(d[0]), "+f"(d[1]), "+f"(d[2]), "+f"(d[3])
        : "r"(a[0]), "r"(a[1]), "r"(a[2]), "r"(a[3]), "r"(b0), "r"(b1));
}

// ============================================================================
// Prep: round 7 tensors to tf32 (3 inputs @ 4M floats, 4 weights @ 1M floats)
// ============================================================================
struct PrepArgs {
    const float* src[7];
    float* dst[7];
    int n4[7];   // element count / 4
};

__global__ __launch_bounds__(256) void prep_kernel(PrepArgs a) {
    const int z = blockIdx.y;
    const float4* s = (const float4*)a.src[z];
    float4* d = (float4*)a.dst[z];
    const int n4 = a.n4[z];
    for (int i = blockIdx.x * 256 + threadIdx.x; i < n4; i += gridDim.x * 256) {
        float4 v = s[i];
        v.x = f2tf32(v.x); v.y = f2tf32(v.y); v.z = f2tf32(v.z); v.w = f2tf32(v.w);
        d[i] = v;
    }
}

// ============================================================================
// GEMM: out = A[M,1024] @ B[1024,N] + bias.  A,B pre-rounded to tf32.
// CTA 128x128, k-tile 32, 3-stage cp.async, 8 warps x (32x64), mma.m16n8k8.
// SCATTER: write head layout [B,H,T,HD] + round to tf32. else plain fp32.
// ============================================================================
#define AL 36              // A row pad (32+4)
#define BL 136             // B row pad (128+8)
#define A_FL (128 * AL)    // 4608 floats
#define B_FL (32 * BL)     // 4352 floats
#define STG (A_FL + B_FL)  // 8960 floats per stage
#define GEMM_SMEM (3 * STG * 4)  // 107520 B
#define NKT (CC / 32)      // 32

template <bool SCATTER>
__device__ __forceinline__ void gemm_body(
    const float* __restrict__ A, const float* __restrict__ B,
    const float* __restrict__ bias, float* __restrict__ out)
{
    extern __shared__ float sm[];
    const int tid  = threadIdx.x;
    const int lane = tid & 31;
    const int w    = tid >> 5;
    const int g    = lane >> 2;
    const int t    = lane & 3;
    const int wm   = w >> 1;          // 0..3 : 32-row strip
    const int wn   = w & 1;           // 0..1 : 64-col strip
    const int m0   = blockIdx.y * 128;
    const int n0   = blockIdx.x * 128;

    float acc[2][8][4];
#pragma unroll
    for (int mi = 0; mi < 2; mi++)
#pragma unroll
        for (int ni = 0; ni < 8; ni++)
#pragma unroll
            for (int j = 0; j < 4; j++) acc[mi][ni][j] = 0.0f;

    const int ar  = tid >> 3;          // A: 0..127 over 2 iters? (1024 ids)
    const int ac4 = (tid & 7) * 4;
    const int brr = tid >> 5;          // B row base
    const int bc4 = (tid & 31) * 4;

    auto issue = [&](int kt, int s) {
        float* As = sm + s * STG;
        float* Bs = As + A_FL;
        const int k0 = kt * 32;
#pragma unroll
        for (int p = 0; p < 4; p++) {
            int r = ar + p * 32;       // 0..127
            cp16(&As[r * AL + ac4], &A[(size_t)(m0 + r) * CC + k0 + ac4]);
        }
#pragma unroll
        for (int p = 0; p < 4; p++) {
            int r = brr + p * 8;       // 0..31
            cp16(&Bs[r * BL + bc4], &B[(size_t)(k0 + r) * CC + n0 + bc4]);
        }
        CP_COMMIT;
    };

    issue(0, 0);
    issue(1, 1);

    for (int kt = 0; kt < NKT; kt++) {
        if (kt + 2 < NKT) { CP_WAIT1; } else { CP_WAIT0; }
        __syncthreads();
        if (kt + 2 < NKT) issue(kt + 2, (kt + 2) % 3);

        const float* As = sm + (kt % 3) * STG;
        const float* Bs = As + A_FL;

#pragma unroll
        for (int kb = 0; kb < 4; kb++) {
            uint32_t a[2][4];
#pragma unroll
            for (int mi = 0; mi < 2; mi++) {
                const int rbase = wm * 32 + mi * 16;
                a[mi][0] = __float_as_uint(As[(rbase + g)     * AL + kb * 8 + t]);
                a[mi][1] = __float_as_uint(As[(rbase + g + 8) * AL + kb * 8 + t]);
                a[mi][2] = __float_as_uint(As[(rbase + g)     * AL + kb * 8 + t + 4]);
                a[mi][3] = __float_as_uint(As[(rbase + g + 8) * AL + kb * 8 + t + 4]);
            }
#pragma unroll
            for (int ni = 0; ni < 8; ni++) {
                const int cb = wn * 64 + ni * 8 + g;
                uint32_t b0 = __float_as_uint(Bs[(kb * 8 + t)     * BL + cb]);
                uint32_t b1 = __float_as_uint(Bs[(kb * 8 + t + 4) * BL + cb]);
                mma_tf32(acc[0][ni], a[0], b0, b1);
                mma_tf32(acc[1][ni], a[1], b0, b1);
            }
        }
    }

    // epilogue: direct register -> global (float2 per row-pair block)
#pragma unroll
    for (int mi = 0; mi < 2; mi++) {
        const int r0 = m0 + wm * 32 + mi * 16 + g;
        const int r1 = r0 + 8;
#pragma unroll
        for (int ni = 0; ni < 8; ni++) {
            const int col = n0 + wn * 64 + ni * 8 + 2 * t;
            float bx = bias[col], by = bias[col + 1];
            float2 u0 = make_float2(acc[mi][ni][0] + bx, acc[mi][ni][1] + by);
            float2 u1 = make_float2(acc[mi][ni][2] + bx, acc[mi][ni][3] + by);
            if (SCATTER) {
                u0.x = f2tf32(u0.x); u0.y = f2tf32(u0.y);
                u1.x = f2tf32(u1.x); u1.y = f2tf32(u1.y);
                const int h = col >> 6;
                const int d = col & 63;
                const int b0i = r0 >> 11, t0i = r0 & 2047;
                const int b1i = r1 >> 11, t1i = r1 & 2047;
                *(float2*)&out[(((size_t)(b0i * HH + h)) * TT + t0i) * HD + d] = u0;
                *(float2*)&out[(((size_t)(b1i * HH + h)) * TT + t1i) * HD + d] = u1;
            } else {
                *(float2*)&out[(size_t)r0 * CC + col] = u0;
                *(float2*)&out[(size_t)r1 * CC + col] = u1;
            }
        }
    }
}

struct QKVArgs {
    const float* X[3];
    const float* W[3];
    const float* Bv[3];
    float* O[3];
};

__global__ __launch_bounds__(256, 2) void gemm_qkv_kernel(QKVArgs args) {
    const int z = blockIdx.z;
    gemm_body<true>(args.X[z], args.W[z], args.Bv[z], args.O[z]);
}

__global__ __launch_bounds__(256, 2) void gemm_proj_kernel(
    const float* __restrict__ X, const float* __restrict__ W,
    const float* __restrict__ bias, float* __restrict__ out) {
    gemm_body<false>(X, W, bias, out);
}

// ============================================================================
// Flash attention (R4, unchanged except Y store rounds to tf32 for proj GEMM)
// ============================================================================
#define BRQ 128
#define QPLD 68
#define KLD  68
#define VLD  72
#define CSCL 0.18033688f  // 0.125 * log2(e)

#define ATTN_SMEM ((BRQ * QPLD + 2 * 64 * KLD + 2 * 64 * VLD) * 4)

__global__ __launch_bounds__(256) void attn_kernel(
    const float* __restrict__ Q, const float* __restrict__ K,
    const float* __restrict__ V, float* __restrict__ Y)
{
    extern __shared__ float sm[];
    float* qp_s = sm;
    float* k_s  = qp_s + BRQ * QPLD;
    float* v_s  = k_s + 2 * 64 * KLD;

    const int tid  = threadIdx.x;
    const int lane = tid & 31;
    const int w    = tid >> 5;
    const int g    = lane >> 2;
    const int t    = lane & 3;
    const int w16  = w * 16;

    const int bh = blockIdx.y;
    const int qt = (int)gridDim.x - 1 - (int)blockIdx.x;
    const int q0 = qt * BRQ;
    const int nkt = 2 * qt + 2;

    {
        const float* Kb = K + ((size_t)bh * TT) * HD;
        const float* Vb = V + ((size_t)bh * TT) * HD;
#pragma unroll
        for (int p = 0; p < 4; p++) {
            int id = tid + p * 256;
            int r = id >> 4, c = (id & 15) * 4;
            cp16(&k_s[r * KLD + c], &Kb[r * HD + c]);
            cp16(&v_s[r * VLD + c], &Vb[r * HD + c]);
        }
        CP_COMMIT;
    }

    {
        const float* Qb = Q + ((size_t)bh * TT + q0) * HD;
#pragma unroll
        for (int p = 0; p < 8; p++) {
            int id = tid + p * 256;
            int r = id >> 4, c = (id & 15) * 4;
            *(float4*)&qp_s[r * QPLD + c] = *(const float4*)&Qb[r * HD + c];
        }
    }
    __syncthreads();

    uint32_t qa[8][4];
#pragma unroll
    for (int kb = 0; kb < 8; kb++) {
        qa[kb][0] = __float_as_uint(qp_s[(w16 + g)     * QPLD + kb * 8 + t]);
        qa[kb][1] = __float_as_uint(qp_s[(w16 + g + 8) * QPLD + kb * 8 + t]);
        qa[kb][2] = __float_as_uint(qp_s[(w16 + g)     * QPLD + kb * 8 + t + 4]);
        qa[kb][3] = __float_as_uint(qp_s[(w16 + g + 8) * QPLD + kb * 8 + t + 4]);
    }

    float oc[8][4];
#pragma unroll
    for (int i = 0; i < 8; i++)
#pragma unroll
        for (int j = 0; j < 4; j++) oc[i][j] = 0.0f;
    float m0 = -1e30f, m1 = -1e30f, l0 = 0.0f, l1 = 0.0f;

    const int rg0 = q0 + w16 + g;
    const int rg1 = rg0 + 8;

    for (int kt = 0; kt < nkt; kt++) {
        const int buf = kt & 1;
        CP_WAIT0;
        __syncthreads();

        if (kt + 1 < nkt) {
            const float* Kb = K + ((size_t)bh * TT + (kt + 1) * 64) * HD;
            const float* Vb = V + ((size_t)bh * TT + (kt + 1) * 64) * HD;
            float* kd = k_s + (buf ^ 1) * 64 * KLD;
            float* vd = v_s + (buf ^ 1) * 64 * VLD;
#pragma unroll
            for (int p = 0; p < 4; p++) {
                int id = tid + p * 256;
                int r = id >> 4, c = (id & 15) * 4;
                cp16(&kd[r * KLD + c], &Kb[r * HD + c]);
                cp16(&vd[r * VLD + c], &Vb[r * HD + c]);
            }
            CP_COMMIT;
        }

        const float* kb_s = k_s + buf * 64 * KLD;
        const float* vb_s = v_s + buf * 64 * VLD;

        float sc[8][4];
#pragma unroll
        for (int nb = 0; nb < 8; nb++)
#pragma unroll
            for (int j = 0; j < 4; j++) sc[nb][j] = 0.0f;

#pragma unroll
        for (int kb = 0; kb < 8; kb++) {
#pragma unroll
            for (int nb = 0; nb < 8; nb++) {
                uint32_t b0 = __float_as_uint(kb_s[(nb * 8 + g) * KLD + kb * 8 + t]);
                uint32_t b1 = __float_as_uint(kb_s[(nb * 8 + g) * KLD + kb * 8 + t + 4]);
                mma_tf32(sc[nb], qa[kb], b0, b1);
            }
        }

        if (kt >= nkt - 2) {
            const int kbase = kt * 64;
#pragma unroll
            for (int nb = 0; nb < 8; nb++) {
                int kg = kbase + nb * 8 + 2 * t;
                if (kg > rg0)     sc[nb][0] = -1e30f;
                if (kg + 1 > rg0) sc[nb][1] = -1e30f;
                if (kg > rg1)     sc[nb][2] = -1e30f;
                if (kg + 1 > rg1) sc[nb][3] = -1e30f;
            }
        }

        float rm0 = -1e30f, rm1 = -1e30f;
#pragma unroll
        for (int nb = 0; nb < 8; nb++) {
            rm0 = fmaxf(rm0, fmaxf(sc[nb][0], sc[nb][1]));
            rm1 = fmaxf(rm1, fmaxf(sc[nb][2], sc[nb][3]));
        }
        rm0 = fmaxf(rm0, __shfl_xor_sync(0xffffffffu, rm0, 1));
        rm0 = fmaxf(rm0, __shfl_xor_sync(0xffffffffu, rm0, 2));
        rm1 = fmaxf(rm1, __shfl_xor_sync(0xffffffffu, rm1, 1));
        rm1 = fmaxf(rm1, __shfl_xor_sync(0xffffffffu, rm1, 2));

        float nm0 = fmaxf(m0, rm0 * CSCL);
        float nm1 = fmaxf(m1, rm1 * CSCL);
        float corr0 = fexp2(m0 - nm0);
        float corr1 = fexp2(m1 - nm1);

        float s0 = 0.0f, s1 = 0.0f;
#pragma unroll
        for (int nb = 0; nb < 8; nb++) {
            float p0 = fexp2(sc[nb][0] * CSCL - nm0);
            float p1 = fexp2(sc[nb][1] * CSCL - nm0);
            float p2 = fexp2(sc[nb][2] * CSCL - nm1);
            float p3 = fexp2(sc[nb][3] * CSCL - nm1);
            s0 += p0 + p1;
            s1 += p2 + p3;
            float2 u0 = make_float2(f2tf32(p0), f2tf32(p1));
            float2 u1 = make_float2(f2tf32(p2), f2tf32(p3));
            *(float2*)&qp_s[(w16 + g)     * QPLD + nb * 8 + 2 * t] = u0;
            *(float2*)&qp_s[(w16 + g + 8) * QPLD + nb * 8 + 2 * t] = u1;
        }
        s0 += __shfl_xor_sync(0xffffffffu, s0, 1);
        s0 += __shfl_xor_sync(0xffffffffu, s0, 2);
        s1 += __shfl_xor_sync(0xffffffffu, s1, 1);
        s1 += __shfl_xor_sync(0xffffffffu, s1, 2);

        l0 = l0 * corr0 + s0;
        l1 = l1 * corr1 + s1;
        m0 = nm0;
        m1 = nm1;

#pragma unroll
        for (int db = 0; db < 8; db++) {
            oc[db][0] *= corr0; oc[db][1] *= corr0;
            oc[db][2] *= corr1; oc[db][3] *= corr1;
        }

        __syncwarp();

#pragma unroll
        for (int kb = 0; kb < 8; kb++) {
            uint32_t pa[4];
            pa[0] = __float_as_uint(qp_s[(w16 + g)     * QPLD + kb * 8 + t]);
            pa[1] = __float_as_uint(qp_s[(w16 + g + 8) * QPLD + kb * 8 + t]);
            pa[2] = __float_as_uint(qp_s[(w16 + g)     * QPLD + kb * 8 + t + 4]);
            pa[3] = __float_as_uint(qp_s[(w16 + g + 8) * QPLD + kb * 8 + t + 4]);
#pragma unroll
            for (int db = 0; db < 8; db++) {
                uint32_t b0 = __float_as_uint(vb_s[(kb * 8 + t)     * VLD + db * 8 + g]);
                uint32_t b1 = __float_as_uint(vb_s[(kb * 8 + t + 4) * VLD + db * 8 + g]);
                mma_tf32(oc[db], pa, b0, b1);
            }
        }
        __syncwarp();
    }

    const float r0 = 1.0f / l0;
    const float r1 = 1.0f / l1;
    const int b = bh >> 4, h = bh & 15;
    float* Yb = Y + ((size_t)(b * TT + q0 + w16)) * CC + h * HD;
#pragma unroll
    for (int db = 0; db < 8; db++) {
        float2 u0 = make_float2(f2tf32(oc[db][0] * r0), f2tf32(oc[db][1] * r0));
        float2 u1 = make_float2(f2tf32(oc[db][2] * r1), f2tf32(oc[db][3] * r1));
        *(float2*)&Yb[(size_t)g * CC + db * 8 + 2 * t] = u0;
        *(float2*)&Yb[(size_t)(g + 8) * CC + db * 8 + 2 * t] = u1;
    }
}

// ============================================================================
// launch
// ============================================================================
extern "C" void kernel_launch(void* const* d_in, const int* in_sizes, int n_in,
                              void* d_out, int out_size)
{
    const float* query = (const float*)d_in[0];
    const float* key_  = (const float*)d_in[1];
    const float* value = (const float*)d_in[2];
    const float* Wq = (const float*)d_in[4];
    const float* bq = (const float*)d_in[5];
    const float* Wk = (const float*)d_in[6];
    const float* bk = (const float*)d_in[7];
    const float* Wv = (const float*)d_in[8];
    const float* bv = (const float*)d_in[9];
    const float* Wp = (const float*)d_in[10];
    const float* bp = (const float*)d_in[11];
    float* out = (float*)d_out;

    float *Qp, *Kp, *Vp, *Yp, *Xr, *Wr;
    cudaGetSymbolAddress((void**)&Qp, g_Q);
    cudaGetSymbolAddress((void**)&Kp, g_K);
    cudaGetSymbolAddress((void**)&Vp, g_V);
    cudaGetSymbolAddress((void**)&Yp, g_Y);
    cudaGetSymbolAddress((void**)&Xr, g_Xr);
    cudaGetSymbolAddress((void**)&Wr, g_Wr);

    static bool attr_done = false;
    if (!attr_done) {
        cudaFuncSetAttribute((const void*)gemm_qkv_kernel,
                             cudaFuncAttributeMaxDynamicSharedMemorySize, GEMM_SMEM);
        cudaFuncSetAttribute((const void*)gemm_proj_kernel,
                             cudaFuncAttributeMaxDynamicSharedMemorySize, GEMM_SMEM);
        cudaFuncSetAttribute((const void*)attn_kernel,
                             cudaFuncAttributeMaxDynamicSharedMemorySize, ATTN_SMEM);
        attr_done = true;
    }

    const size_t XN = (size_t)MTOT * CC;   // 4M
    const size_t WN = (size_t)CC * CC;     // 1M

    PrepArgs pa;
    pa.src[0] = query; pa.dst[0] = Xr;              pa.n4[0] = (int)(XN / 4);
    pa.src[1] = key_;  pa.dst[1] = Xr + XN;         pa.n4[1] = (int)(XN / 4);
    pa.src[2] = value; pa.dst[2] = Xr + 2 * XN;     pa.n4[2] = (int)(XN / 4);
    pa.src[3] = Wq;    pa.dst[3] = Wr;              pa.n4[3] = (int)(WN / 4);
    pa.src[4] = Wk;    pa.dst[4] = Wr + WN;         pa.n4[4] = (int)(WN / 4);
    pa.src[5] = Wv;    pa.dst[5] = Wr + 2 * WN;     pa.n4[5] = (int)(WN / 4);
    pa.src[6] = Wp;    pa.dst[6] = Wr + 3 * WN;     pa.n4[6] = (int)(WN / 4);
    prep_kernel<<<dim3(148, 7), 256>>>(pa);

    QKVArgs args;
    args.X[0] = Xr;            args.X[1] = Xr + XN;      args.X[2] = Xr + 2 * XN;
    args.W[0] = Wr;            args.W[1] = Wr + WN;      args.W[2] = Wr + 2 * WN;
    args.Bv[0] = bq;           args.Bv[1] = bk;          args.Bv[2] = bv;
    args.O[0] = Qp;            args.O[1] = Kp;           args.O[2] = Vp;

    gemm_qkv_kernel<<<dim3(CC / 128, MTOT / 128, 3), 256, GEMM_SMEM>>>(args);
    attn_kernel<<<dim3(TT / BRQ, BB * HH), 256, ATTN_SMEM>>>(Qp, Kp, Vp, Yp);
    gemm_proj_kernel<<<dim3(CC / 128, MTOT / 128), 256, GEMM_SMEM>>>(
        Yp, Wr + 3 * WN, bp, out);
}